// round 1
// baseline (speedup 1.0000x reference)
#include <cuda_runtime.h>
#include <math.h>

#define TOK   12544
#define BATCH 4
#define HDIM  56
#define WDIM  56
#define LSEQ  3136
#define DI    256
#define NWIN  256

// ---------------- scratch (device globals; no allocation) ----------------
__device__ float g_xn[TOK*128];
__device__ float g_qkv[TOK*384];
__device__ float g_awb[TOK*128];
__device__ float g_attn[TOK*128];
__device__ float g_xz[TOK*512];
__device__ float g_xc[TOK*256];
__device__ float g_dbl[TOK*40];
__device__ float g_dt[TOK*256];
__device__ float g_y[TOK*256];
__device__ float g_mamba[TOK*128];
__device__ float g_cat[TOK*256];
__device__ float g_x1[TOK*128];
__device__ float g_h2[TOK*128];
__device__ float g_hid[TOK*512];

// ---------------- LayerNorm (warp per token, C=128) ----------------
__global__ void ln_kernel(const float* __restrict__ in, const float* __restrict__ g,
                          const float* __restrict__ b, float* __restrict__ out) {
    int warp = (blockIdx.x * blockDim.x + threadIdx.x) >> 5;
    int lane = threadIdx.x & 31;
    if (warp >= TOK) return;
    float4 v = ((const float4*)(in + (size_t)warp*128))[lane];
    float s = v.x+v.y+v.z+v.w;
    #pragma unroll
    for (int o=16;o;o>>=1) s += __shfl_xor_sync(~0u, s, o);
    float mean = s * (1.f/128.f);
    float dx=v.x-mean, dy=v.y-mean, dz=v.z-mean, dw=v.w-mean;
    float q = dx*dx+dy*dy+dz*dz+dw*dw;
    #pragma unroll
    for (int o=16;o;o>>=1) q += __shfl_xor_sync(~0u, q, o);
    float rstd = rsqrtf(q*(1.f/128.f) + 1e-5f);
    float4 gv = ((const float4*)g)[lane];
    float4 bv = ((const float4*)b)[lane];
    float4 ov;
    ov.x = dx*rstd*gv.x + bv.x;
    ov.y = dy*rstd*gv.y + bv.y;
    ov.z = dz*rstd*gv.z + bv.z;
    ov.w = dw*rstd*gv.w + bv.w;
    ((float4*)(out + (size_t)warp*128))[lane] = ov;
}

// ---------------- generic SGEMM: C[M,N] = A[M,K] @ W[N,K]^T (+bias, epilogue) ----------------
// EPI: 0 none, 1 gelu, 2 gate-fuse (e0=x, e1=attn, e2=mamba), 3 residual add (e0)
__device__ __forceinline__ float gelu_f(float x){ return 0.5f*x*(1.f+erff(x*0.70710678118f)); }

template<int EPI>
__global__ void gemm64(const float* __restrict__ A, const float* __restrict__ W,
                       const float* __restrict__ bias, float* __restrict__ C,
                       int N, int K,
                       const float* __restrict__ e0, const float* __restrict__ e1,
                       const float* __restrict__ e2)
{
    __shared__ float As[16][68];
    __shared__ float Bs[16][68];
    int tid = threadIdx.x;
    int bm = blockIdx.y * 64, bn = blockIdx.x * 64;
    int tx = tid & 15, ty = tid >> 4;
    int lr = tid >> 2, lc = (tid & 3) * 4;
    float acc[4][4] = {};
    const float* Ap = A + (size_t)(bm+lr)*K + lc;
    int wr = bn + lr;
    const float* Wp = W + (size_t)wr*K + lc;
    bool wok = wr < N;
    for (int k0 = 0; k0 < K; k0 += 16) {
        float4 av = *(const float4*)(Ap + k0);
        float4 wv = wok ? *(const float4*)(Wp + k0) : make_float4(0.f,0.f,0.f,0.f);
        As[lc+0][lr]=av.x; As[lc+1][lr]=av.y; As[lc+2][lr]=av.z; As[lc+3][lr]=av.w;
        Bs[lc+0][lr]=wv.x; Bs[lc+1][lr]=wv.y; Bs[lc+2][lr]=wv.z; Bs[lc+3][lr]=wv.w;
        __syncthreads();
        #pragma unroll
        for (int kk=0;kk<16;kk++){
            float4 a = *(const float4*)&As[kk][ty*4];
            float4 bq = *(const float4*)&Bs[kk][tx*4];
            float ar[4]={a.x,a.y,a.z,a.w}, br[4]={bq.x,bq.y,bq.z,bq.w};
            #pragma unroll
            for (int i=0;i<4;i++)
                #pragma unroll
                for (int j=0;j<4;j++) acc[i][j] = fmaf(ar[i], br[j], acc[i][j]);
        }
        __syncthreads();
    }
    #pragma unroll
    for (int i=0;i<4;i++){
        int m = bm + ty*4 + i;
        #pragma unroll
        for (int j=0;j<4;j++){
            int n = bn + tx*4 + j;
            if (n >= N) continue;
            float v = acc[i][j];
            if (bias) v += bias[n];
            size_t idx = (size_t)m*N + n;
            if (EPI == 1) {
                v = gelu_f(v);
            } else if (EPI == 2) {
                float gt = 1.f/(1.f+__expf(-v));
                v = e0[idx] + gt*e1[idx] + (1.f-gt)*e2[idx];
            } else if (EPI == 3) {
                v = e0[idx] + v;
            }
            C[idx] = v;
        }
    }
}

// ---------------- window attention: one block per (window, head) ----------------
__global__ void attn_kernel(const float* __restrict__ rpb) {
    int w = blockIdx.x >> 2;
    int head = blockIdx.x & 3;
    int b = w >> 6, wh = (w >> 3) & 7, ww = w & 7;
    __shared__ float qs[49][32], ks[49][32], vs[49][32];
    __shared__ float sc[49][49];
    int tid = threadIdx.x;
    const float scale = 0.17677669529663689f;   // 1/sqrt(32)
    for (int i = tid; i < 49*32; i += 128) {
        int n = i >> 5, d = i & 31;
        int t = ((b*56 + wh*7 + n/7)*56 + ww*7 + n%7);
        const float* base = g_qkv + (size_t)t*384 + head*32 + d;
        qs[n][d] = base[0] * scale;
        ks[n][d] = base[128];
        vs[n][d] = base[256];
    }
    __syncthreads();
    for (int idx = tid; idx < 49*49; idx += 128) {
        int i = idx/49, j = idx%49;
        float s = 0.f;
        const float4* qp = (const float4*)qs[i];
        const float4* kp = (const float4*)ks[j];
        #pragma unroll
        for (int k=0;k<8;k++){ float4 a=qp[k], c=kp[k]; s += a.x*c.x+a.y*c.y+a.z*c.z+a.w*c.w; }
        int dr = i/7 - j/7 + 6, dc = i%7 - j%7 + 6;
        sc[i][j] = s + rpb[(dr*13+dc)*4 + head];
    }
    __syncthreads();
    if (tid < 49) {
        int i = tid;
        float m = -1e30f;
        for (int j=0;j<49;j++) m = fmaxf(m, sc[i][j]);
        float sum = 0.f;
        for (int j=0;j<49;j++){ float e=__expf(sc[i][j]-m); sc[i][j]=e; sum+=e; }
        float inv = 1.f/sum;
        for (int j=0;j<49;j++) sc[i][j] *= inv;
    }
    __syncthreads();
    for (int idx = tid; idx < 49*32; idx += 128) {
        int i = idx >> 5, d = idx & 31;
        float o = 0.f;
        for (int j=0;j<49;j++) o += sc[i][j]*vs[j][d];
        int t = ((b*56 + wh*7 + i/7)*56 + ww*7 + i%7);
        g_awb[(size_t)t*128 + head*32 + d] = o;
    }
}

// ---------------- causal depthwise conv (k=4) + SiLU over flattened HW ----------------
__global__ void conv_kernel(const float* __restrict__ cw, const float* __restrict__ cb) {
    int idx = blockIdx.x*blockDim.x + threadIdx.x;
    if (idx >= TOK*256) return;
    int t = idx >> 8, d = idx & 255;
    int b = t / LSEQ, l = t % LSEQ;
    float acc = cb[d];
    #pragma unroll
    for (int j=0;j<4;j++){
        int ll = l - 3 + j;
        if (ll >= 0) acc = fmaf(cw[d*4+j], g_xz[((size_t)(b*LSEQ+ll))*512 + d], acc);
    }
    float sg = 1.f/(1.f+__expf(-acc));
    g_xc[idx] = acc * sg;
}

// ---------------- dt = softplus(dbl[:, :8] @ dt_proj_w^T + b) ----------------
__global__ void dtproj_kernel(const float* __restrict__ wt, const float* __restrict__ bias){
    int idx = blockIdx.x*blockDim.x + threadIdx.x;
    if (idx >= TOK*256) return;
    int t = idx >> 8, d = idx & 255;
    float acc = bias[d];
    const float* r = g_dbl + (size_t)t*40;
    const float* wr = wt + d*8;
    #pragma unroll
    for (int k=0;k<8;k++) acc = fmaf(r[k], wr[k], acc);
    float sp = (acc > 20.f) ? acc : log1pf(__expf(acc));
    g_dt[idx] = sp;
}

// ---------------- selective scan: warp = 2 channels x 16 states, chunked smem reduce ----------------
__global__ void scan_kernel(const float* __restrict__ A_log, const float* __restrict__ Dp){
    __shared__ float part[8*32*33];
    int warp = threadIdx.x >> 5, lane = threadIdx.x & 31;
    int gw = blockIdx.x * 8 + warp;        // 0..511
    int b = gw >> 7;
    int dbase = (gw & 127) * 2;
    int d = dbase + (lane >> 4);
    int s = lane & 15;
    float Aval = -__expf(A_log[d*16 + s]);
    float dp0 = Dp[dbase], dp1 = Dp[dbase+1];
    float h = 0.f;
    float* pp = part + warp*32*33 + lane*33;
    float* wp = part + warp*32*33;
    int tb = b * LSEQ;
    for (int base = 0; base < LSEQ; base += 32) {
        #pragma unroll 1
        for (int g = 0; g < 32; g += 8) {
            float dtv[8], xcv[8], Bv[8], Cv[8];
            #pragma unroll
            for (int u=0;u<8;u++){
                int t = tb + base + g + u;
                dtv[u] = g_dt[(size_t)t*256 + d];
                xcv[u] = g_xc[(size_t)t*256 + d];
                Bv[u]  = g_dbl[(size_t)t*40 + 8 + s];
                Cv[u]  = g_dbl[(size_t)t*40 + 24 + s];
            }
            #pragma unroll
            for (int u=0;u<8;u++){
                float a = __expf(dtv[u]*Aval);
                h = a*h + dtv[u]*Bv[u]*xcv[u];
                pp[g+u] = h * Cv[u];
            }
        }
        __syncwarp();
        {
            int lu = lane;
            int t = tb + base + lu;
            #pragma unroll
            for (int c2=0;c2<2;c2++){
                float ys = 0.f;
                #pragma unroll
                for (int ss=0; ss<16; ss++) ys += wp[(c2*16+ss)*33 + lu];
                int d2 = dbase + c2;
                float xcv2 = g_xc[(size_t)t*256 + d2];
                float zv = g_xz[(size_t)t*512 + 256 + d2];
                float yv = ys + xcv2 * (c2 ? dp1 : dp0);
                float sg = 1.f/(1.f+__expf(-zv));
                g_y[(size_t)t*256 + d2] = yv * zv * sg;
            }
        }
        __syncwarp();
    }
}

// ---------------- concat attn||mamba for gate GEMM ----------------
__global__ void concat_kernel(){
    int idx = blockIdx.x*blockDim.x + threadIdx.x;
    if (idx >= TOK*256) return;
    int t = idx >> 8, c = idx & 255;
    g_cat[idx] = (c < 128) ? g_attn[(size_t)t*128 + c] : g_mamba[(size_t)t*128 + c - 128];
}

// ---------------- launch ----------------
extern "C" void kernel_launch(void* const* d_in, const int* in_sizes, int n_in,
                              void* d_out, int out_size) {
    const float* x        = (const float*)d_in[0];
    const float* ln1_g    = (const float*)d_in[1];
    const float* ln1_b    = (const float*)d_in[2];
    const float* qkv_w    = (const float*)d_in[3];
    const float* qkv_b    = (const float*)d_in[4];
    const float* rpb      = (const float*)d_in[5];
    const float* proj_w   = (const float*)d_in[6];
    const float* proj_b   = (const float*)d_in[7];
    const float* in_w     = (const float*)d_in[8];
    const float* in_b     = (const float*)d_in[9];
    const float* conv_w   = (const float*)d_in[10];
    const float* conv_b   = (const float*)d_in[11];
    const float* xproj_w  = (const float*)d_in[12];
    const float* dtw      = (const float*)d_in[13];
    const float* dtb      = (const float*)d_in[14];
    const float* A_log    = (const float*)d_in[15];
    const float* Dp       = (const float*)d_in[16];
    const float* out_w    = (const float*)d_in[17];
    const float* out_b    = (const float*)d_in[18];
    const float* gate_w   = (const float*)d_in[19];
    const float* gate_b   = (const float*)d_in[20];
    const float* ln2_g    = (const float*)d_in[21];
    const float* ln2_b    = (const float*)d_in[22];
    const float* mlp_w1   = (const float*)d_in[23];
    const float* mlp_b1   = (const float*)d_in[24];
    const float* mlp_w2   = (const float*)d_in[25];
    const float* mlp_b2   = (const float*)d_in[26];
    float* out = (float*)d_out;

    float *xn, *qkv, *awb, *attn, *xz, *xc, *dbl, *dt, *y, *mamba, *cat, *x1, *h2, *hid;
    cudaGetSymbolAddress((void**)&xn,    g_xn);
    cudaGetSymbolAddress((void**)&qkv,   g_qkv);
    cudaGetSymbolAddress((void**)&awb,   g_awb);
    cudaGetSymbolAddress((void**)&attn,  g_attn);
    cudaGetSymbolAddress((void**)&xz,    g_xz);
    cudaGetSymbolAddress((void**)&xc,    g_xc);
    cudaGetSymbolAddress((void**)&dbl,   g_dbl);
    cudaGetSymbolAddress((void**)&dt,    g_dt);
    cudaGetSymbolAddress((void**)&y,     g_y);
    cudaGetSymbolAddress((void**)&mamba, g_mamba);
    cudaGetSymbolAddress((void**)&cat,   g_cat);
    cudaGetSymbolAddress((void**)&x1,    g_x1);
    cudaGetSymbolAddress((void**)&h2,    g_h2);
    cudaGetSymbolAddress((void**)&hid,   g_hid);

    const int MB = TOK/64;   // 196

    // LN1
    ln_kernel<<<TOK/8, 256>>>(x, ln1_g, ln1_b, xn);
    // qkv GEMM
    gemm64<0><<<dim3(6, MB), 256>>>(xn, qkv_w, qkv_b, qkv, 384, 128, nullptr, nullptr, nullptr);
    // window attention
    attn_kernel<<<NWIN*4, 128>>>(rpb);
    // proj GEMM -> attn_out
    gemm64<0><<<dim3(2, MB), 256>>>(awb, proj_w, proj_b, attn, 128, 128, nullptr, nullptr, nullptr);
    // in_proj GEMM -> xz
    gemm64<0><<<dim3(8, MB), 256>>>(xn, in_w, in_b, xz, 512, 128, nullptr, nullptr, nullptr);
    // causal conv + silu -> xc
    conv_kernel<<<TOK, 256>>>(conv_w, conv_b);
    // x_proj GEMM -> dbl (no bias)
    gemm64<0><<<dim3(1, MB), 256>>>(xc, xproj_w, nullptr, dbl, 40, 256, nullptr, nullptr, nullptr);
    // dt_proj + softplus -> dt
    dtproj_kernel<<<TOK, 256>>>(dtw, dtb);
    // selective scan (+ D skip + silu(z) gate) -> y
    scan_kernel<<<64, 256>>>(A_log, Dp);
    // out_proj GEMM -> mamba_out
    gemm64<0><<<dim3(2, MB), 256>>>(y, out_w, out_b, mamba, 128, 256, nullptr, nullptr, nullptr);
    // concat
    concat_kernel<<<TOK, 256>>>();
    // gate GEMM + fused sigmoid blend + residual -> x1
    gemm64<2><<<dim3(2, MB), 256>>>(cat, gate_w, gate_b, x1, 128, 256, x, attn, mamba);
    // LN2
    ln_kernel<<<TOK/8, 256>>>(x1, ln2_g, ln2_b, h2);
    // MLP1 + gelu
    gemm64<1><<<dim3(8, MB), 256>>>(h2, mlp_w1, mlp_b1, hid, 512, 128, nullptr, nullptr, nullptr);
    // MLP2 + residual -> out
    gemm64<3><<<dim3(2, MB), 256>>>(hid, mlp_w2, mlp_b2, out, 128, 512, x1, nullptr, nullptr);

    (void)in_sizes; (void)n_in; (void)out_size;
}

// round 2
// speedup vs baseline: 2.4331x; 2.4331x over previous
#include <cuda_runtime.h>
#include <math.h>

#define TOK   12544
#define BATCH 4
#define LSEQ  3136
#define NWIN  256
#define NCH   49      // chunks per batch sequence
#define CH    64      // chunk length

// ---------------- scratch (device globals; no allocation) ----------------
__device__ float g_xn[TOK*128];
__device__ float g_qkv[TOK*384];
__device__ float g_awb[TOK*128];
__device__ float g_attn[TOK*128];
__device__ float g_xz[TOK*512];
__device__ float g_xc[TOK*256];
__device__ float g_dbl[TOK*40];
__device__ float g_dt[TOK*256];
__device__ float g_y[TOK*256];
__device__ float g_mamba[TOK*128];
__device__ float g_x1[TOK*128];
__device__ float g_h2[TOK*128];
__device__ float g_hid[TOK*512];
__device__ float g_hend[BATCH*NCH*256*16];
__device__ float g_hin[BATCH*NCH*256*16];
__device__ float g_sumdt[BATCH*NCH*256];

// ---------------- LayerNorm (warp per token, C=128) ----------------
__global__ void ln_kernel(const float* __restrict__ in, const float* __restrict__ g,
                          const float* __restrict__ b, float* __restrict__ out) {
    int warp = (blockIdx.x * blockDim.x + threadIdx.x) >> 5;
    int lane = threadIdx.x & 31;
    if (warp >= TOK) return;
    float4 v = ((const float4*)(in + (size_t)warp*128))[lane];
    float s = v.x+v.y+v.z+v.w;
    #pragma unroll
    for (int o=16;o;o>>=1) s += __shfl_xor_sync(~0u, s, o);
    float mean = s * (1.f/128.f);
    float dx=v.x-mean, dy=v.y-mean, dz=v.z-mean, dw=v.w-mean;
    float q = dx*dx+dy*dy+dz*dz+dw*dw;
    #pragma unroll
    for (int o=16;o;o>>=1) q += __shfl_xor_sync(~0u, q, o);
    float rstd = rsqrtf(q*(1.f/128.f) + 1e-5f);
    float4 gv = ((const float4*)g)[lane];
    float4 bv = ((const float4*)b)[lane];
    float4 ov;
    ov.x = dx*rstd*gv.x + bv.x;
    ov.y = dy*rstd*gv.y + bv.y;
    ov.z = dz*rstd*gv.z + bv.z;
    ov.w = dw*rstd*gv.w + bv.w;
    ((float4*)(out + (size_t)warp*128))[lane] = ov;
}

// ---------------- double-buffered SGEMM: C[M,N] = A[M,K] @ W[N,K]^T ----------------
// EPI: 0 none, 1 gelu, 2 gate-fuse (e0=x, e1=attn, e2=mamba), 3 residual add (e0)
// GATHER: A operand gathered as [e1 | e2] concat (K must be 256)
__device__ __forceinline__ float gelu_f(float x){ return 0.5f*x*(1.f+erff(x*0.70710678118f)); }

template<int EPI, int GATHER>
__global__ __launch_bounds__(256)
void gemm64(const float* __restrict__ A, const float* __restrict__ W,
            const float* __restrict__ bias, float* __restrict__ C,
            int N, int K,
            const float* __restrict__ e0, const float* __restrict__ e1,
            const float* __restrict__ e2)
{
    __shared__ float As[2][16][68];
    __shared__ float Bs[2][16][68];
    int tid = threadIdx.x;
    int bm = blockIdx.y * 64, bn = blockIdx.x * 64;
    int tx = tid & 15, ty = tid >> 4;
    int lr = tid >> 2, lc = (tid & 3) * 4;
    float acc[4][4] = {};
    int row = bm + lr;
    const float* Ap = A + (size_t)row*K + lc;
    int wr = bn + lr;
    const float* Wp = W + (size_t)wr*K + lc;
    bool wok = wr < N;

    float4 av, wv;
    // load k-tile 0
    if (GATHER) {
        int k = lc;
        av = (k < 128) ? *(const float4*)(e1 + (size_t)row*128 + k)
                       : *(const float4*)(e2 + (size_t)row*128 + k - 128);
    } else {
        av = *(const float4*)(Ap);
    }
    wv = wok ? *(const float4*)(Wp) : make_float4(0.f,0.f,0.f,0.f);
    int buf = 0;
    As[0][lc+0][lr]=av.x; As[0][lc+1][lr]=av.y; As[0][lc+2][lr]=av.z; As[0][lc+3][lr]=av.w;
    Bs[0][lc+0][lr]=wv.x; Bs[0][lc+1][lr]=wv.y; Bs[0][lc+2][lr]=wv.z; Bs[0][lc+3][lr]=wv.w;
    __syncthreads();

    for (int k0 = 0; k0 < K; k0 += 16) {
        float4 an, wn;
        bool more = (k0 + 16) < K;
        if (more) {
            int knext = k0 + 16;
            if (GATHER) {
                int k = lc + knext;
                an = (k < 128) ? *(const float4*)(e1 + (size_t)row*128 + k)
                               : *(const float4*)(e2 + (size_t)row*128 + k - 128);
            } else {
                an = *(const float4*)(Ap + knext);
            }
            wn = wok ? *(const float4*)(Wp + knext) : make_float4(0.f,0.f,0.f,0.f);
        }
        #pragma unroll
        for (int kk=0;kk<16;kk++){
            float4 a = *(const float4*)&As[buf][kk][ty*4];
            float4 bq = *(const float4*)&Bs[buf][kk][tx*4];
            float ar[4]={a.x,a.y,a.z,a.w}, br[4]={bq.x,bq.y,bq.z,bq.w};
            #pragma unroll
            for (int i=0;i<4;i++)
                #pragma unroll
                for (int j=0;j<4;j++) acc[i][j] = fmaf(ar[i], br[j], acc[i][j]);
        }
        if (more) {
            int nb = buf ^ 1;
            As[nb][lc+0][lr]=an.x; As[nb][lc+1][lr]=an.y; As[nb][lc+2][lr]=an.z; As[nb][lc+3][lr]=an.w;
            Bs[nb][lc+0][lr]=wn.x; Bs[nb][lc+1][lr]=wn.y; Bs[nb][lc+2][lr]=wn.z; Bs[nb][lc+3][lr]=wn.w;
            __syncthreads();
            buf = nb;
        }
    }

    #pragma unroll
    for (int i=0;i<4;i++){
        int m = bm + ty*4 + i;
        #pragma unroll
        for (int j=0;j<4;j++){
            int n = bn + tx*4 + j;
            if (n >= N) continue;
            float v = acc[i][j];
            if (bias) v += bias[n];
            size_t idx = (size_t)m*N + n;
            if (EPI == 1) {
                v = gelu_f(v);
            } else if (EPI == 2) {
                float gt = 1.f/(1.f+__expf(-v));
                v = e0[idx] + gt*e1[idx] + (1.f-gt)*e2[idx];
            } else if (EPI == 3) {
                v = e0[idx] + v;
            }
            C[idx] = v;
        }
    }
}

// ---------------- window attention: one block per (window, head) ----------------
__global__ void attn_kernel(const float* __restrict__ rpb) {
    int w = blockIdx.x >> 2;
    int head = blockIdx.x & 3;
    int b = w >> 6, wh = (w >> 3) & 7, ww = w & 7;
    __shared__ float qs[49][32], ks[49][32], vs[49][32];
    __shared__ float sc[49][49];
    int tid = threadIdx.x;
    const float scale = 0.17677669529663689f;   // 1/sqrt(32)
    for (int i = tid; i < 49*32; i += 128) {
        int n = i >> 5, d = i & 31;
        int t = ((b*56 + wh*7 + n/7)*56 + ww*7 + n%7);
        const float* base = g_qkv + (size_t)t*384 + head*32 + d;
        qs[n][d] = base[0] * scale;
        ks[n][d] = base[128];
        vs[n][d] = base[256];
    }
    __syncthreads();
    for (int idx = tid; idx < 49*49; idx += 128) {
        int i = idx/49, j = idx%49;
        float s = 0.f;
        const float4* qp = (const float4*)qs[i];
        const float4* kp = (const float4*)ks[j];
        #pragma unroll
        for (int k=0;k<8;k++){ float4 a=qp[k], c=kp[k]; s += a.x*c.x+a.y*c.y+a.z*c.z+a.w*c.w; }
        int dr = i/7 - j/7 + 6, dc = i%7 - j%7 + 6;
        sc[i][j] = s + rpb[(dr*13+dc)*4 + head];
    }
    __syncthreads();
    if (tid < 49) {
        int i = tid;
        float m = -1e30f;
        for (int j=0;j<49;j++) m = fmaxf(m, sc[i][j]);
        float sum = 0.f;
        for (int j=0;j<49;j++){ float e=__expf(sc[i][j]-m); sc[i][j]=e; sum+=e; }
        float inv = 1.f/sum;
        for (int j=0;j<49;j++) sc[i][j] *= inv;
    }
    __syncthreads();
    for (int idx = tid; idx < 49*32; idx += 128) {
        int i = idx >> 5, d = idx & 31;
        float o = 0.f;
        for (int j=0;j<49;j++) o += sc[i][j]*vs[j][d];
        int t = ((b*56 + wh*7 + i/7)*56 + ww*7 + i%7);
        g_awb[(size_t)t*128 + head*32 + d] = o;
    }
}

// ---------------- causal depthwise conv (k=4) + SiLU ----------------
__global__ void conv_kernel(const float* __restrict__ cw, const float* __restrict__ cb) {
    int idx = blockIdx.x*blockDim.x + threadIdx.x;
    if (idx >= TOK*256) return;
    int t = idx >> 8, d = idx & 255;
    int b = t / LSEQ, l = t % LSEQ;
    float acc = cb[d];
    #pragma unroll
    for (int j=0;j<4;j++){
        int ll = l - 3 + j;
        if (ll >= 0) acc = fmaf(cw[d*4+j], g_xz[((size_t)(b*LSEQ+ll))*512 + d], acc);
    }
    float sg = 1.f/(1.f+__expf(-acc));
    g_xc[idx] = acc * sg;
}

// ---------------- dt = softplus(dbl[:, :8] @ dt_proj_w^T + b) ----------------
__global__ void dtproj_kernel(const float* __restrict__ wt, const float* __restrict__ bias){
    int idx = blockIdx.x*blockDim.x + threadIdx.x;
    if (idx >= TOK*256) return;
    int t = idx >> 8, d = idx & 255;
    float acc = bias[d];
    const float* r = g_dbl + (size_t)t*40;
    const float* wr = wt + d*8;
    #pragma unroll
    for (int k=0;k<8;k++) acc = fmaf(r[k], wr[k], acc);
    float sp = (acc > 20.f) ? acc : log1pf(__expf(acc));
    g_dt[idx] = sp;
}

// ============ chunk-parallel selective scan ============
// mapping: warp handles (b, chunk, channel-pair); lane = (c2 in {0,1}, s in 0..15)

// Phase 1: per-chunk local scan from h=0 -> h_end, and sum(dt) per (chunk, d).
__global__ __launch_bounds__(256) void scan_phase1(const float* __restrict__ A_log){
    int gw = (blockIdx.x*blockDim.x + threadIdx.x) >> 5;   // 0..25087
    int lane = threadIdx.x & 31;
    int dpair = gw & 127;
    int chunk = (gw >> 7) % NCH;
    int b = gw / (128*NCH);
    int d = dpair*2 + (lane >> 4);
    int s = lane & 15;
    float Aval = -__expf(A_log[d*16 + s]);
    float h = 0.f, sd = 0.f;
    int t0 = b*LSEQ + chunk*CH;
    for (int g = 0; g < CH; g += 8) {
        float dtv[8], xcv[8], Bv[8];
        #pragma unroll
        for (int u=0;u<8;u++){
            int t = t0 + g + u;
            dtv[u] = g_dt[(size_t)t*256 + d];
            xcv[u] = g_xc[(size_t)t*256 + d];
            Bv[u]  = g_dbl[(size_t)t*40 + 8 + s];
        }
        #pragma unroll
        for (int u=0;u<8;u++){
            sd += dtv[u];
            float a = __expf(dtv[u]*Aval);
            h = a*h + dtv[u]*Bv[u]*xcv[u];
        }
    }
    size_t hidx = ((size_t)(b*NCH + chunk)*256 + d)*16 + s;
    g_hend[hidx] = h;
    if (s == 0) g_sumdt[(b*NCH + chunk)*256 + d] = sd;
}

// Phase 2: serial chain across chunks (49 steps): h_in[chunk], h = exp(A*sumdt)*h + h_end.
__global__ __launch_bounds__(256) void scan_phase2(const float* __restrict__ A_log){
    int gw = (blockIdx.x*blockDim.x + threadIdx.x) >> 5;   // 0..511
    int lane = threadIdx.x & 31;
    int b = gw >> 7;
    int dpair = gw & 127;
    int d = dpair*2 + (lane >> 4);
    int s = lane & 15;
    float Aval = -__expf(A_log[d*16 + s]);
    float h = 0.f;
    for (int c = 0; c < NCH; c++) {
        size_t hidx = ((size_t)(b*NCH + c)*256 + d)*16 + s;
        g_hin[hidx] = h;
        float sd = g_sumdt[(b*NCH + c)*256 + d];
        h = __expf(Aval*sd)*h + g_hend[hidx];
    }
}

// Phase 3: re-scan each chunk from h_in, emit y (with D skip + silu(z) gate).
__global__ __launch_bounds__(256) void scan_phase3(const float* __restrict__ A_log,
                                                   const float* __restrict__ Dp){
    __shared__ float part[8*32*33];
    int warp = threadIdx.x >> 5, lane = threadIdx.x & 31;
    int gw = blockIdx.x * 8 + warp;
    int dpair = gw & 127;
    int chunk = (gw >> 7) % NCH;
    int b = gw / (128*NCH);
    int dbase = dpair*2;
    int d = dbase + (lane >> 4);
    int s = lane & 15;
    float Aval = -__expf(A_log[d*16 + s]);
    float dp0 = Dp[dbase], dp1 = Dp[dbase+1];
    size_t hidx = ((size_t)(b*NCH + chunk)*256 + d)*16 + s;
    float h = g_hin[hidx];
    float* pp = part + warp*32*33 + lane*33;
    float* wp = part + warp*32*33;
    int tb = b*LSEQ + chunk*CH;
    #pragma unroll 1
    for (int half = 0; half < 2; half++) {
        int base = half*32;
        #pragma unroll 1
        for (int g = 0; g < 32; g += 8) {
            float dtv[8], xcv[8], Bv[8], Cv[8];
            #pragma unroll
            for (int u=0;u<8;u++){
                int t = tb + base + g + u;
                dtv[u] = g_dt[(size_t)t*256 + d];
                xcv[u] = g_xc[(size_t)t*256 + d];
                Bv[u]  = g_dbl[(size_t)t*40 + 8 + s];
                Cv[u]  = g_dbl[(size_t)t*40 + 24 + s];
            }
            #pragma unroll
            for (int u=0;u<8;u++){
                float a = __expf(dtv[u]*Aval);
                h = a*h + dtv[u]*Bv[u]*xcv[u];
                pp[g+u] = h * Cv[u];
            }
        }
        __syncwarp();
        {
            int lu = lane;
            int t = tb + base + lu;
            #pragma unroll
            for (int c2=0;c2<2;c2++){
                float ys = 0.f;
                #pragma unroll
                for (int ss=0; ss<16; ss++) ys += wp[(c2*16+ss)*33 + lu];
                int d2 = dbase + c2;
                float xcv2 = g_xc[(size_t)t*256 + d2];
                float zv = g_xz[(size_t)t*512 + 256 + d2];
                float yv = ys + xcv2 * (c2 ? dp1 : dp0);
                float sg = 1.f/(1.f+__expf(-zv));
                g_y[(size_t)t*256 + d2] = yv * zv * sg;
            }
        }
        __syncwarp();
    }
}

// ---------------- launch ----------------
extern "C" void kernel_launch(void* const* d_in, const int* in_sizes, int n_in,
                              void* d_out, int out_size) {
    const float* x        = (const float*)d_in[0];
    const float* ln1_g    = (const float*)d_in[1];
    const float* ln1_b    = (const float*)d_in[2];
    const float* qkv_w    = (const float*)d_in[3];
    const float* qkv_b    = (const float*)d_in[4];
    const float* rpb      = (const float*)d_in[5];
    const float* proj_w   = (const float*)d_in[6];
    const float* proj_b   = (const float*)d_in[7];
    const float* in_w     = (const float*)d_in[8];
    const float* in_b     = (const float*)d_in[9];
    const float* conv_w   = (const float*)d_in[10];
    const float* conv_b   = (const float*)d_in[11];
    const float* xproj_w  = (const float*)d_in[12];
    const float* dtw      = (const float*)d_in[13];
    const float* dtb      = (const float*)d_in[14];
    const float* A_log    = (const float*)d_in[15];
    const float* Dp       = (const float*)d_in[16];
    const float* out_w    = (const float*)d_in[17];
    const float* out_b    = (const float*)d_in[18];
    const float* gate_w   = (const float*)d_in[19];
    const float* gate_b   = (const float*)d_in[20];
    const float* ln2_g    = (const float*)d_in[21];
    const float* ln2_b    = (const float*)d_in[22];
    const float* mlp_w1   = (const float*)d_in[23];
    const float* mlp_b1   = (const float*)d_in[24];
    const float* mlp_w2   = (const float*)d_in[25];
    const float* mlp_b2   = (const float*)d_in[26];
    float* out = (float*)d_out;

    float *xn, *qkv, *awb, *attn, *xz, *y, *mamba, *x1, *h2, *hid;
    cudaGetSymbolAddress((void**)&xn,    g_xn);
    cudaGetSymbolAddress((void**)&qkv,   g_qkv);
    cudaGetSymbolAddress((void**)&awb,   g_awb);
    cudaGetSymbolAddress((void**)&attn,  g_attn);
    cudaGetSymbolAddress((void**)&xz,    g_xz);
    cudaGetSymbolAddress((void**)&y,     g_y);
    cudaGetSymbolAddress((void**)&mamba, g_mamba);
    cudaGetSymbolAddress((void**)&x1,    g_x1);
    cudaGetSymbolAddress((void**)&h2,    g_h2);
    cudaGetSymbolAddress((void**)&hid,   g_hid);
    float *xc, *dbl;
    cudaGetSymbolAddress((void**)&xc,  g_xc);
    cudaGetSymbolAddress((void**)&dbl, g_dbl);

    const int MB = TOK/64;   // 196

    // LN1
    ln_kernel<<<TOK/8, 256>>>(x, ln1_g, ln1_b, xn);
    // qkv GEMM
    gemm64<0,0><<<dim3(6, MB), 256>>>(xn, qkv_w, qkv_b, qkv, 384, 128, nullptr, nullptr, nullptr);
    // window attention
    attn_kernel<<<NWIN*4, 128>>>(rpb);
    // proj GEMM -> attn_out
    gemm64<0,0><<<dim3(2, MB), 256>>>(awb, proj_w, proj_b, attn, 128, 128, nullptr, nullptr, nullptr);
    // in_proj GEMM -> xz
    gemm64<0,0><<<dim3(8, MB), 256>>>(xn, in_w, in_b, xz, 512, 128, nullptr, nullptr, nullptr);
    // causal conv + silu -> xc
    conv_kernel<<<TOK, 256>>>(conv_w, conv_b);
    // x_proj GEMM -> dbl (no bias)
    gemm64<0,0><<<dim3(1, MB), 256>>>(xc, xproj_w, nullptr, dbl, 40, 256, nullptr, nullptr, nullptr);
    // dt_proj + softplus -> dt
    dtproj_kernel<<<TOK, 256>>>(dtw, dtb);
    // chunk-parallel selective scan
    scan_phase1<<<(BATCH*NCH*128)/8, 256>>>(A_log);
    scan_phase2<<<64, 256>>>(A_log);
    scan_phase3<<<(BATCH*NCH*128)/8, 256>>>(A_log, Dp);
    // out_proj GEMM -> mamba_out
    gemm64<0,0><<<dim3(2, MB), 256>>>(y, out_w, out_b, mamba, 128, 256, nullptr, nullptr, nullptr);
    // gate GEMM (A gathered from attn||mamba) + fused sigmoid blend + residual -> x1
    gemm64<2,1><<<dim3(2, MB), 256>>>(nullptr, gate_w, gate_b, x1, 128, 256, x, attn, mamba);
    // LN2
    ln_kernel<<<TOK/8, 256>>>(x1, ln2_g, ln2_b, h2);
    // MLP1 + gelu
    gemm64<1,0><<<dim3(8, MB), 256>>>(h2, mlp_w1, mlp_b1, hid, 512, 128, nullptr, nullptr, nullptr);
    // MLP2 + residual -> out
    gemm64<3,0><<<dim3(2, MB), 256>>>(hid, mlp_w2, mlp_b2, out, 128, 512, x1, nullptr, nullptr);

    (void)in_sizes; (void)n_in; (void)out_size;
}

// round 3
// speedup vs baseline: 2.5088x; 1.0311x over previous
#include <cuda_runtime.h>
#include <math.h>

#define TOK   12544
#define BATCH 4
#define LSEQ  3136
#define NWIN  256
#define NCH   49      // chunks per batch sequence
#define CH    64      // chunk length

// ---------------- scratch (device globals; no allocation) ----------------
__device__ float g_xn[TOK*128];
__device__ float g_qkv[TOK*384];
__device__ float g_awb[TOK*128];
__device__ float g_attn[TOK*128];
__device__ float g_xz[TOK*512];
__device__ float g_xc[TOK*256];
__device__ float g_dbl[TOK*40];
__device__ float g_dt[TOK*256];
__device__ float g_y[TOK*256];
__device__ float g_mamba[TOK*128];
__device__ float g_x1[TOK*128];
__device__ float g_h2[TOK*128];
__device__ float g_hid[TOK*512];
__device__ float g_hend[BATCH*NCH*256*16];
__device__ float g_hin[BATCH*NCH*256*16];
__device__ float g_sumdt[BATCH*NCH*256];

__device__ __forceinline__ float gelu_f(float x){ return 0.5f*x*(1.f+erff(x*0.70710678118f)); }

// ---------------- LayerNorm (warp per token, C=128) ----------------
__global__ void ln_kernel(const float* __restrict__ in, const float* __restrict__ g,
                          const float* __restrict__ b, float* __restrict__ out) {
    int warp = (blockIdx.x * blockDim.x + threadIdx.x) >> 5;
    int lane = threadIdx.x & 31;
    if (warp >= TOK) return;
    float4 v = ((const float4*)(in + (size_t)warp*128))[lane];
    float s = v.x+v.y+v.z+v.w;
    #pragma unroll
    for (int o=16;o;o>>=1) s += __shfl_xor_sync(~0u, s, o);
    float mean = s * (1.f/128.f);
    float dx=v.x-mean, dy=v.y-mean, dz=v.z-mean, dw=v.w-mean;
    float q = dx*dx+dy*dy+dz*dz+dw*dw;
    #pragma unroll
    for (int o=16;o;o>>=1) q += __shfl_xor_sync(~0u, q, o);
    float rstd = rsqrtf(q*(1.f/128.f) + 1e-5f);
    float4 gv = ((const float4*)g)[lane];
    float4 bv = ((const float4*)b)[lane];
    float4 ov;
    ov.x = dx*rstd*gv.x + bv.x;
    ov.y = dy*rstd*gv.y + bv.y;
    ov.z = dz*rstd*gv.z + bv.z;
    ov.w = dw*rstd*gv.w + bv.w;
    ((float4*)(out + (size_t)warp*128))[lane] = ov;
}

// ================= gemm128: 128x128 tile, 8x8 micro-tile =================
// C[M,N] = A[M,K] @ W[N,K]^T + bias. N multiple of 128, M multiple of 128.
// EPI: 0 none, 1 gelu
template<int EPI>
__global__ __launch_bounds__(256)
void gemm128(const float* __restrict__ A, const float* __restrict__ W,
             const float* __restrict__ bias, float* __restrict__ C,
             int N, int K)
{
    __shared__ float As[2][16][136];
    __shared__ float Bs[2][16][136];
    int tid = threadIdx.x;
    int bm = blockIdx.y * 128, bn = blockIdx.x * 128;
    int tx = tid & 15, ty = tid >> 4;
    int lr = tid >> 1, lc = (tid & 1) * 8;
    const float* Ap = A + (size_t)(bm + lr)*K + lc;
    const float* Wp = W + (size_t)(bn + lr)*K + lc;
    float acc[8][8] = {};

    float4 a0 = *(const float4*)(Ap),   a1 = *(const float4*)(Ap + 4);
    float4 w0 = *(const float4*)(Wp),   w1 = *(const float4*)(Wp + 4);
    int buf = 0;
    As[0][lc+0][lr]=a0.x; As[0][lc+1][lr]=a0.y; As[0][lc+2][lr]=a0.z; As[0][lc+3][lr]=a0.w;
    As[0][lc+4][lr]=a1.x; As[0][lc+5][lr]=a1.y; As[0][lc+6][lr]=a1.z; As[0][lc+7][lr]=a1.w;
    Bs[0][lc+0][lr]=w0.x; Bs[0][lc+1][lr]=w0.y; Bs[0][lc+2][lr]=w0.z; Bs[0][lc+3][lr]=w0.w;
    Bs[0][lc+4][lr]=w1.x; Bs[0][lc+5][lr]=w1.y; Bs[0][lc+6][lr]=w1.z; Bs[0][lc+7][lr]=w1.w;
    __syncthreads();

    for (int k0 = 0; k0 < K; k0 += 16) {
        bool more = (k0 + 16) < K;
        if (more) {
            a0 = *(const float4*)(Ap + k0 + 16); a1 = *(const float4*)(Ap + k0 + 20);
            w0 = *(const float4*)(Wp + k0 + 16); w1 = *(const float4*)(Wp + k0 + 20);
        }
        #pragma unroll
        for (int kk = 0; kk < 16; kk++) {
            float4 x0 = *(const float4*)&As[buf][kk][ty*4];
            float4 x1 = *(const float4*)&As[buf][kk][64 + ty*4];
            float4 y0 = *(const float4*)&Bs[buf][kk][tx*4];
            float4 y1 = *(const float4*)&Bs[buf][kk][64 + tx*4];
            float ar[8] = {x0.x,x0.y,x0.z,x0.w,x1.x,x1.y,x1.z,x1.w};
            float br[8] = {y0.x,y0.y,y0.z,y0.w,y1.x,y1.y,y1.z,y1.w};
            #pragma unroll
            for (int i=0;i<8;i++)
                #pragma unroll
                for (int j=0;j<8;j++) acc[i][j] = fmaf(ar[i], br[j], acc[i][j]);
        }
        if (more) {
            int nb = buf ^ 1;
            As[nb][lc+0][lr]=a0.x; As[nb][lc+1][lr]=a0.y; As[nb][lc+2][lr]=a0.z; As[nb][lc+3][lr]=a0.w;
            As[nb][lc+4][lr]=a1.x; As[nb][lc+5][lr]=a1.y; As[nb][lc+6][lr]=a1.z; As[nb][lc+7][lr]=a1.w;
            Bs[nb][lc+0][lr]=w0.x; Bs[nb][lc+1][lr]=w0.y; Bs[nb][lc+2][lr]=w0.z; Bs[nb][lc+3][lr]=w0.w;
            Bs[nb][lc+4][lr]=w1.x; Bs[nb][lc+5][lr]=w1.y; Bs[nb][lc+6][lr]=w1.z; Bs[nb][lc+7][lr]=w1.w;
            __syncthreads();
            buf = nb;
        }
    }

    #pragma unroll
    for (int i=0;i<8;i++){
        int m = bm + ((i<4) ? (ty*4 + i) : (64 + ty*4 + i - 4));
        #pragma unroll
        for (int g=0; g<2; g++){
            int c = bn + g*64 + tx*4;
            float4 bv = bias ? *(const float4*)(bias + c) : make_float4(0.f,0.f,0.f,0.f);
            float4 v;
            v.x = acc[i][g*4+0] + bv.x;
            v.y = acc[i][g*4+1] + bv.y;
            v.z = acc[i][g*4+2] + bv.z;
            v.w = acc[i][g*4+3] + bv.w;
            if (EPI == 1) { v.x=gelu_f(v.x); v.y=gelu_f(v.y); v.z=gelu_f(v.z); v.w=gelu_f(v.w); }
            *(float4*)(C + (size_t)m*N + c) = v;
        }
    }
}

// ================= gemm64n: 64x128 tile, 4x8 micro-tile =================
// EPI: 0 none, 2 gate-fuse (e0=x, e1=attn, e2=mamba), 3 residual add (e0)
// GATHER: A gathered as [e1 | e2] concat (K must be 256)
template<int EPI, int GATHER>
__global__ __launch_bounds__(256)
void gemm64n(const float* __restrict__ A, const float* __restrict__ W,
             const float* __restrict__ bias, float* __restrict__ C,
             int N, int K,
             const float* __restrict__ e0, const float* __restrict__ e1,
             const float* __restrict__ e2)
{
    __shared__ float As[2][16][72];
    __shared__ float Bs[2][16][136];
    int tid = threadIdx.x;
    int bm = blockIdx.y * 64, bn = blockIdx.x * 128;
    int tx = tid & 15, ty = tid >> 4;
    int ar_ = tid >> 2, ac_ = (tid & 3) * 4;      // A loader: row 0..63, col {0,4,8,12}
    int wr_ = tid >> 1, wc_ = (tid & 1) * 8;      // B loader: row 0..127, col {0,8}
    int arow = bm + ar_;
    const float* Ap = A + (size_t)arow*K + ac_;
    const float* Wp = W + (size_t)(bn + wr_)*K + wc_;
    float acc[4][8] = {};

    float4 av, w0, w1;
    if (GATHER) {
        int k = ac_;
        av = (k < 128) ? *(const float4*)(e1 + (size_t)arow*128 + k)
                       : *(const float4*)(e2 + (size_t)arow*128 + k - 128);
    } else {
        av = *(const float4*)(Ap);
    }
    w0 = *(const float4*)(Wp); w1 = *(const float4*)(Wp + 4);
    int buf = 0;
    As[0][ac_+0][ar_]=av.x; As[0][ac_+1][ar_]=av.y; As[0][ac_+2][ar_]=av.z; As[0][ac_+3][ar_]=av.w;
    Bs[0][wc_+0][wr_]=w0.x; Bs[0][wc_+1][wr_]=w0.y; Bs[0][wc_+2][wr_]=w0.z; Bs[0][wc_+3][wr_]=w0.w;
    Bs[0][wc_+4][wr_]=w1.x; Bs[0][wc_+5][wr_]=w1.y; Bs[0][wc_+6][wr_]=w1.z; Bs[0][wc_+7][wr_]=w1.w;
    __syncthreads();

    for (int k0 = 0; k0 < K; k0 += 16) {
        bool more = (k0 + 16) < K;
        if (more) {
            if (GATHER) {
                int k = ac_ + k0 + 16;
                av = (k < 128) ? *(const float4*)(e1 + (size_t)arow*128 + k)
                               : *(const float4*)(e2 + (size_t)arow*128 + k - 128);
            } else {
                av = *(const float4*)(Ap + k0 + 16);
            }
            w0 = *(const float4*)(Wp + k0 + 16); w1 = *(const float4*)(Wp + k0 + 20);
        }
        #pragma unroll
        for (int kk = 0; kk < 16; kk++) {
            float4 x0 = *(const float4*)&As[buf][kk][ty*4];
            float4 y0 = *(const float4*)&Bs[buf][kk][tx*4];
            float4 y1 = *(const float4*)&Bs[buf][kk][64 + tx*4];
            float ar[4] = {x0.x,x0.y,x0.z,x0.w};
            float br[8] = {y0.x,y0.y,y0.z,y0.w,y1.x,y1.y,y1.z,y1.w};
            #pragma unroll
            for (int i=0;i<4;i++)
                #pragma unroll
                for (int j=0;j<8;j++) acc[i][j] = fmaf(ar[i], br[j], acc[i][j]);
        }
        if (more) {
            int nb = buf ^ 1;
            As[nb][ac_+0][ar_]=av.x; As[nb][ac_+1][ar_]=av.y; As[nb][ac_+2][ar_]=av.z; As[nb][ac_+3][ar_]=av.w;
            Bs[nb][wc_+0][wr_]=w0.x; Bs[nb][wc_+1][wr_]=w0.y; Bs[nb][wc_+2][wr_]=w0.z; Bs[nb][wc_+3][wr_]=w0.w;
            Bs[nb][wc_+4][wr_]=w1.x; Bs[nb][wc_+5][wr_]=w1.y; Bs[nb][wc_+6][wr_]=w1.z; Bs[nb][wc_+7][wr_]=w1.w;
            __syncthreads();
            buf = nb;
        }
    }

    #pragma unroll
    for (int i=0;i<4;i++){
        int m = bm + ty*4 + i;
        #pragma unroll
        for (int g=0; g<2; g++){
            int c = bn + g*64 + tx*4;
            float4 bv = bias ? *(const float4*)(bias + c) : make_float4(0.f,0.f,0.f,0.f);
            float4 v;
            v.x = acc[i][g*4+0] + bv.x;
            v.y = acc[i][g*4+1] + bv.y;
            v.z = acc[i][g*4+2] + bv.z;
            v.w = acc[i][g*4+3] + bv.w;
            size_t idx = (size_t)m*N + c;
            if (EPI == 2) {
                float4 r0 = *(const float4*)(e0 + idx);
                float4 r1 = *(const float4*)(e1 + idx);
                float4 r2 = *(const float4*)(e2 + idx);
                float gx = 1.f/(1.f+__expf(-v.x));
                float gy = 1.f/(1.f+__expf(-v.y));
                float gz = 1.f/(1.f+__expf(-v.z));
                float gw = 1.f/(1.f+__expf(-v.w));
                v.x = r0.x + gx*r1.x + (1.f-gx)*r2.x;
                v.y = r0.y + gy*r1.y + (1.f-gy)*r2.y;
                v.z = r0.z + gz*r1.z + (1.f-gz)*r2.z;
                v.w = r0.w + gw*r1.w + (1.f-gw)*r2.w;
            } else if (EPI == 3) {
                float4 r0 = *(const float4*)(e0 + idx);
                v.x += r0.x; v.y += r0.y; v.z += r0.z; v.w += r0.w;
            }
            *(float4*)(C + idx) = v;
        }
    }
}

// ---------------- small-N GEMM (x_proj, N=40): 64x64 tile ----------------
__global__ __launch_bounds__(256)
void gemm64(const float* __restrict__ A, const float* __restrict__ W,
            const float* __restrict__ bias, float* __restrict__ C,
            int N, int K)
{
    __shared__ float As[2][16][68];
    __shared__ float Bs[2][16][68];
    int tid = threadIdx.x;
    int bm = blockIdx.y * 64, bn = blockIdx.x * 64;
    int tx = tid & 15, ty = tid >> 4;
    int lr = tid >> 2, lc = (tid & 3) * 4;
    float acc[4][4] = {};
    const float* Ap = A + (size_t)(bm+lr)*K + lc;
    int wr = bn + lr;
    const float* Wp = W + (size_t)wr*K + lc;
    bool wok = wr < N;

    float4 av = *(const float4*)(Ap);
    float4 wv = wok ? *(const float4*)(Wp) : make_float4(0.f,0.f,0.f,0.f);
    int buf = 0;
    As[0][lc+0][lr]=av.x; As[0][lc+1][lr]=av.y; As[0][lc+2][lr]=av.z; As[0][lc+3][lr]=av.w;
    Bs[0][lc+0][lr]=wv.x; Bs[0][lc+1][lr]=wv.y; Bs[0][lc+2][lr]=wv.z; Bs[0][lc+3][lr]=wv.w;
    __syncthreads();

    for (int k0 = 0; k0 < K; k0 += 16) {
        bool more = (k0 + 16) < K;
        if (more) {
            av = *(const float4*)(Ap + k0 + 16);
            wv = wok ? *(const float4*)(Wp + k0 + 16) : make_float4(0.f,0.f,0.f,0.f);
        }
        #pragma unroll
        for (int kk=0;kk<16;kk++){
            float4 a = *(const float4*)&As[buf][kk][ty*4];
            float4 bq = *(const float4*)&Bs[buf][kk][tx*4];
            float ar[4]={a.x,a.y,a.z,a.w}, br[4]={bq.x,bq.y,bq.z,bq.w};
            #pragma unroll
            for (int i=0;i<4;i++)
                #pragma unroll
                for (int j=0;j<4;j++) acc[i][j] = fmaf(ar[i], br[j], acc[i][j]);
        }
        if (more) {
            int nb = buf ^ 1;
            As[nb][lc+0][lr]=av.x; As[nb][lc+1][lr]=av.y; As[nb][lc+2][lr]=av.z; As[nb][lc+3][lr]=av.w;
            Bs[nb][lc+0][lr]=wv.x; Bs[nb][lc+1][lr]=wv.y; Bs[nb][lc+2][lr]=wv.z; Bs[nb][lc+3][lr]=wv.w;
            __syncthreads();
            buf = nb;
        }
    }
    #pragma unroll
    for (int i=0;i<4;i++){
        int m = bm + ty*4 + i;
        #pragma unroll
        for (int j=0;j<4;j++){
            int n = bn + tx*4 + j;
            if (n >= N) continue;
            float v = acc[i][j];
            if (bias) v += bias[n];
            C[(size_t)m*N + n] = v;
        }
    }
}

// ---------------- window attention: one block per (window, head) ----------------
__global__ void attn_kernel(const float* __restrict__ rpb) {
    int w = blockIdx.x >> 2;
    int head = blockIdx.x & 3;
    int b = w >> 6, wh = (w >> 3) & 7, ww = w & 7;
    __shared__ float qs[49][32], ks[49][32], vs[49][32];
    __shared__ float sc[49][49];
    int tid = threadIdx.x;
    const float scale = 0.17677669529663689f;   // 1/sqrt(32)
    for (int i = tid; i < 49*32; i += 128) {
        int n = i >> 5, d = i & 31;
        int t = ((b*56 + wh*7 + n/7)*56 + ww*7 + n%7);
        const float* base = g_qkv + (size_t)t*384 + head*32 + d;
        qs[n][d] = base[0] * scale;
        ks[n][d] = base[128];
        vs[n][d] = base[256];
    }
    __syncthreads();
    for (int idx = tid; idx < 49*49; idx += 128) {
        int i = idx/49, j = idx%49;
        float s = 0.f;
        const float4* qp = (const float4*)qs[i];
        const float4* kp = (const float4*)ks[j];
        #pragma unroll
        for (int k=0;k<8;k++){ float4 a=qp[k], c=kp[k]; s += a.x*c.x+a.y*c.y+a.z*c.z+a.w*c.w; }
        int dr = i/7 - j/7 + 6, dc = i%7 - j%7 + 6;
        sc[i][j] = s + rpb[(dr*13+dc)*4 + head];
    }
    __syncthreads();
    if (tid < 49) {
        int i = tid;
        float m = -1e30f;
        for (int j=0;j<49;j++) m = fmaxf(m, sc[i][j]);
        float sum = 0.f;
        for (int j=0;j<49;j++){ float e=__expf(sc[i][j]-m); sc[i][j]=e; sum+=e; }
        float inv = 1.f/sum;
        for (int j=0;j<49;j++) sc[i][j] *= inv;
    }
    __syncthreads();
    for (int idx = tid; idx < 49*32; idx += 128) {
        int i = idx >> 5, d = idx & 31;
        float o = 0.f;
        for (int j=0;j<49;j++) o += sc[i][j]*vs[j][d];
        int t = ((b*56 + wh*7 + i/7)*56 + ww*7 + i%7);
        g_awb[(size_t)t*128 + head*32 + d] = o;
    }
}

// ---------------- causal depthwise conv (k=4) + SiLU ----------------
__global__ void conv_kernel(const float* __restrict__ cw, const float* __restrict__ cb) {
    int idx = blockIdx.x*blockDim.x + threadIdx.x;
    if (idx >= TOK*256) return;
    int t = idx >> 8, d = idx & 255;
    int b = t / LSEQ, l = t % LSEQ;
    float acc = cb[d];
    #pragma unroll
    for (int j=0;j<4;j++){
        int ll = l - 3 + j;
        if (ll >= 0) acc = fmaf(cw[d*4+j], g_xz[((size_t)(b*LSEQ+ll))*512 + d], acc);
    }
    float sg = 1.f/(1.f+__expf(-acc));
    g_xc[idx] = acc * sg;
}

// ---------------- dt = softplus(dbl[:, :8] @ dt_proj_w^T + b) ----------------
__global__ void dtproj_kernel(const float* __restrict__ wt, const float* __restrict__ bias){
    int idx = blockIdx.x*blockDim.x + threadIdx.x;
    if (idx >= TOK*256) return;
    int t = idx >> 8, d = idx & 255;
    float acc = bias[d];
    const float* r = g_dbl + (size_t)t*40;
    const float* wr = wt + d*8;
    #pragma unroll
    for (int k=0;k<8;k++) acc = fmaf(r[k], wr[k], acc);
    float sp = (acc > 20.f) ? acc : log1pf(__expf(acc));
    g_dt[idx] = sp;
}

// ============ chunk-parallel selective scan ============
__global__ __launch_bounds__(256) void scan_phase1(const float* __restrict__ A_log){
    int gw = (blockIdx.x*blockDim.x + threadIdx.x) >> 5;
    int lane = threadIdx.x & 31;
    int dpair = gw & 127;
    int chunk = (gw >> 7) % NCH;
    int b = gw / (128*NCH);
    int d = dpair*2 + (lane >> 4);
    int s = lane & 15;
    float Aval = -__expf(A_log[d*16 + s]);
    float h = 0.f, sd = 0.f;
    int t0 = b*LSEQ + chunk*CH;
    for (int g = 0; g < CH; g += 8) {
        float dtv[8], xcv[8], Bv[8];
        #pragma unroll
        for (int u=0;u<8;u++){
            int t = t0 + g + u;
            dtv[u] = g_dt[(size_t)t*256 + d];
            xcv[u] = g_xc[(size_t)t*256 + d];
            Bv[u]  = g_dbl[(size_t)t*40 + 8 + s];
        }
        #pragma unroll
        for (int u=0;u<8;u++){
            sd += dtv[u];
            float a = __expf(dtv[u]*Aval);
            h = a*h + dtv[u]*Bv[u]*xcv[u];
        }
    }
    size_t hidx = ((size_t)(b*NCH + chunk)*256 + d)*16 + s;
    g_hend[hidx] = h;
    if (s == 0) g_sumdt[(b*NCH + chunk)*256 + d] = sd;
}

__global__ __launch_bounds__(256) void scan_phase2(const float* __restrict__ A_log){
    int gw = (blockIdx.x*blockDim.x + threadIdx.x) >> 5;
    int lane = threadIdx.x & 31;
    int b = gw >> 7;
    int dpair = gw & 127;
    int d = dpair*2 + (lane >> 4);
    int s = lane & 15;
    float Aval = -__expf(A_log[d*16 + s]);
    float h = 0.f;
    for (int c = 0; c < NCH; c++) {
        size_t hidx = ((size_t)(b*NCH + c)*256 + d)*16 + s;
        g_hin[hidx] = h;
        float sd = g_sumdt[(b*NCH + c)*256 + d];
        h = __expf(Aval*sd)*h + g_hend[hidx];
    }
}

__global__ __launch_bounds__(256) void scan_phase3(const float* __restrict__ A_log,
                                                   const float* __restrict__ Dp){
    __shared__ float part[8*32*33];
    int warp = threadIdx.x >> 5, lane = threadIdx.x & 31;
    int gw = blockIdx.x * 8 + warp;
    int dpair = gw & 127;
    int chunk = (gw >> 7) % NCH;
    int b = gw / (128*NCH);
    int dbase = dpair*2;
    int d = dbase + (lane >> 4);
    int s = lane & 15;
    float Aval = -__expf(A_log[d*16 + s]);
    float dp0 = Dp[dbase], dp1 = Dp[dbase+1];
    size_t hidx = ((size_t)(b*NCH + chunk)*256 + d)*16 + s;
    float h = g_hin[hidx];
    float* pp = part + warp*32*33 + lane*33;
    float* wp = part + warp*32*33;
    int tb = b*LSEQ + chunk*CH;
    #pragma unroll 1
    for (int half = 0; half < 2; half++) {
        int base = half*32;
        #pragma unroll 1
        for (int g = 0; g < 32; g += 8) {
            float dtv[8], xcv[8], Bv[8], Cv[8];
            #pragma unroll
            for (int u=0;u<8;u++){
                int t = tb + base + g + u;
                dtv[u] = g_dt[(size_t)t*256 + d];
                xcv[u] = g_xc[(size_t)t*256 + d];
                Bv[u]  = g_dbl[(size_t)t*40 + 8 + s];
                Cv[u]  = g_dbl[(size_t)t*40 + 24 + s];
            }
            #pragma unroll
            for (int u=0;u<8;u++){
                float a = __expf(dtv[u]*Aval);
                h = a*h + dtv[u]*Bv[u]*xcv[u];
                pp[g+u] = h * Cv[u];
            }
        }
        __syncwarp();
        {
            int lu = lane;
            int t = tb + base + lu;
            #pragma unroll
            for (int c2=0;c2<2;c2++){
                float ys = 0.f;
                #pragma unroll
                for (int ss=0; ss<16; ss++) ys += wp[(c2*16+ss)*33 + lu];
                int d2 = dbase + c2;
                float xcv2 = g_xc[(size_t)t*256 + d2];
                float zv = g_xz[(size_t)t*512 + 256 + d2];
                float yv = ys + xcv2 * (c2 ? dp1 : dp0);
                float sg = 1.f/(1.f+__expf(-zv));
                g_y[(size_t)t*256 + d2] = yv * zv * sg;
            }
        }
        __syncwarp();
    }
}

// ---------------- launch ----------------
extern "C" void kernel_launch(void* const* d_in, const int* in_sizes, int n_in,
                              void* d_out, int out_size) {
    const float* x        = (const float*)d_in[0];
    const float* ln1_g    = (const float*)d_in[1];
    const float* ln1_b    = (const float*)d_in[2];
    const float* qkv_w    = (const float*)d_in[3];
    const float* qkv_b    = (const float*)d_in[4];
    const float* rpb      = (const float*)d_in[5];
    const float* proj_w   = (const float*)d_in[6];
    const float* proj_b   = (const float*)d_in[7];
    const float* in_w     = (const float*)d_in[8];
    const float* in_b     = (const float*)d_in[9];
    const float* conv_w   = (const float*)d_in[10];
    const float* conv_b   = (const float*)d_in[11];
    const float* xproj_w  = (const float*)d_in[12];
    const float* dtw      = (const float*)d_in[13];
    const float* dtb      = (const float*)d_in[14];
    const float* A_log    = (const float*)d_in[15];
    const float* Dp       = (const float*)d_in[16];
    const float* out_w    = (const float*)d_in[17];
    const float* out_b    = (const float*)d_in[18];
    const float* gate_w   = (const float*)d_in[19];
    const float* gate_b   = (const float*)d_in[20];
    const float* ln2_g    = (const float*)d_in[21];
    const float* ln2_b    = (const float*)d_in[22];
    const float* mlp_w1   = (const float*)d_in[23];
    const float* mlp_b1   = (const float*)d_in[24];
    const float* mlp_w2   = (const float*)d_in[25];
    const float* mlp_b2   = (const float*)d_in[26];
    float* out = (float*)d_out;

    float *xn, *qkv, *awb, *attn, *xz, *y, *mamba, *x1, *h2, *hid, *xc, *dbl;
    cudaGetSymbolAddress((void**)&xn,    g_xn);
    cudaGetSymbolAddress((void**)&qkv,   g_qkv);
    cudaGetSymbolAddress((void**)&awb,   g_awb);
    cudaGetSymbolAddress((void**)&attn,  g_attn);
    cudaGetSymbolAddress((void**)&xz,    g_xz);
    cudaGetSymbolAddress((void**)&y,     g_y);
    cudaGetSymbolAddress((void**)&mamba, g_mamba);
    cudaGetSymbolAddress((void**)&x1,    g_x1);
    cudaGetSymbolAddress((void**)&h2,    g_h2);
    cudaGetSymbolAddress((void**)&hid,   g_hid);
    cudaGetSymbolAddress((void**)&xc,    g_xc);
    cudaGetSymbolAddress((void**)&dbl,   g_dbl);

    // LN1
    ln_kernel<<<TOK/8, 256>>>(x, ln1_g, ln1_b, xn);
    // qkv GEMM (N=384)
    gemm128<0><<<dim3(3, 98), 256>>>(xn, qkv_w, qkv_b, qkv, 384, 128);
    // window attention
    attn_kernel<<<NWIN*4, 128>>>(rpb);
    // proj GEMM -> attn_out (N=128)
    gemm64n<0,0><<<dim3(1, 196), 256>>>(awb, proj_w, proj_b, attn, 128, 128, nullptr, nullptr, nullptr);
    // in_proj GEMM -> xz (N=512)
    gemm128<0><<<dim3(4, 98), 256>>>(xn, in_w, in_b, xz, 512, 128);
    // causal conv + silu -> xc
    conv_kernel<<<TOK, 256>>>(conv_w, conv_b);
    // x_proj GEMM -> dbl (N=40)
    gemm64<<<dim3(1, 196), 256>>>(xc, xproj_w, nullptr, dbl, 40, 256);
    // dt_proj + softplus -> dt
    dtproj_kernel<<<TOK, 256>>>(dtw, dtb);
    // chunk-parallel selective scan
    scan_phase1<<<(BATCH*NCH*128)/8, 256>>>(A_log);
    scan_phase2<<<64, 256>>>(A_log);
    scan_phase3<<<(BATCH*NCH*128)/8, 256>>>(A_log, Dp);
    // out_proj GEMM -> mamba_out (N=128, K=256)
    gemm64n<0,0><<<dim3(1, 196), 256>>>(y, out_w, out_b, mamba, 128, 256, nullptr, nullptr, nullptr);
    // gate GEMM (A gathered from attn||mamba) + fused blend + residual -> x1
    gemm64n<2,1><<<dim3(1, 196), 256>>>(nullptr, gate_w, gate_b, x1, 128, 256, x, attn, mamba);
    // LN2
    ln_kernel<<<TOK/8, 256>>>(x1, ln2_g, ln2_b, h2);
    // MLP1 + gelu (N=512)
    gemm128<1><<<dim3(4, 98), 256>>>(h2, mlp_w1, mlp_b1, hid, 512, 128);
    // MLP2 + residual -> out (N=128, K=512)
    gemm64n<3,0><<<dim3(1, 196), 256>>>(hid, mlp_w2, mlp_b2, out, 128, 512, x1, nullptr, nullptr);

    (void)in_sizes; (void)n_in; (void)out_size;
}